// round 16
// baseline (speedup 1.0000x reference)
#include <cuda_runtime.h>
#include <cuda_fp16.h>
#include <cstdint>

#define MAX_NODES 20000
#define MAX_EDGES 160000
#define HID 256
#define NUM_GRAPHS 16

// ---------------- device scratch (static, no runtime alloc) ----------------
__device__ __half g_bufA[MAX_NODES * HID];  // y_nbr projections (fp16)
__device__ __half g_bufB[MAX_NODES * HID];  // y_self projections +bias (fp16)
__device__ int    g_deg[MAX_NODES];
__device__ int    g_rowstart[MAX_NODES];
__device__ int    g_cursor[MAX_NODES];
__device__ int    g_csr[MAX_EDGES];
__device__ float  g_pool[NUM_GRAPHS * HID];
__device__ int    g_bad;                    // !=0 -> index inputs are int32
__device__ int    g_base;                   // CSR allocation ticket

// A operand fp16 (padded to full 128-row tiles); also holds h1/h2 between layers
#define PAD_ROWS (MAX_NODES + 128)
__device__ __half g_Ah[PAD_ROWS * 512];

// transposed fp16 weights: WT[n][k], n in [0,512)
__device__ __half g_WT1h[512 * 512];
__device__ __half g_WT2h[512 * 256];

// ---------------- helpers ----------------
__device__ __forceinline__ uint32_t smem_u32(const void* p) {
    uint32_t a;
    asm("{ .reg .u64 t; cvta.to.shared.u64 t, %1; cvt.u32.u64 %0, t; }"
        : "=r"(a) : "l"(p));
    return a;
}
#define CP_ASYNC16(dst_u32, src_ptr) \
    asm volatile("cp.async.cg.shared.global [%0], [%1], 16;" \
                 :: "r"(dst_u32), "l"(src_ptr))
#define CP_COMMIT() asm volatile("cp.async.commit_group;" ::: "memory")
#define CP_WAIT(N) asm volatile("cp.async.wait_group %0;" :: "n"(N) : "memory")

__device__ __forceinline__ void ldsm_x4(uint32_t* r, uint32_t addr) {
    asm volatile(
        "ldmatrix.sync.aligned.m8n8.x4.shared.b16 {%0,%1,%2,%3}, [%4];"
        : "=r"(r[0]), "=r"(r[1]), "=r"(r[2]), "=r"(r[3]) : "r"(addr));
}

__device__ __forceinline__ int getIdx(const void* p, int i, int is64) {
    if (is64) return (int)((const long long*)p)[i];
    return ((const int*)p)[i];
}

// ---------------- init: zero + dtype probe (one launch) ----------------
__global__ void init_kernel(const void* ei, int ne, int n) {
    int i = blockIdx.x * blockDim.x + threadIdx.x;
    int stride = gridDim.x * blockDim.x;
    if (i == 0) { g_base = 0; }
    for (int j = i; j < n; j += stride) g_deg[j] = 0;
    for (int j = i; j < NUM_GRAPHS * HID; j += stride) g_pool[j] = 0.0f;
    int local = 0;
    for (int e = i; e < ne; e += stride) {
        long long v = ((const long long*)ei)[e];
        if (v < 0 || v >= (long long)n) local = 1;
    }
    if (i == 0) g_bad = 0;
    __threadfence();
    if (__syncthreads_or(local)) {
        if (threadIdx.x == 0) atomicOr(&g_bad, 1);
    }
}

// ---------------- CSR build ----------------
__global__ void edge_hist(const void* __restrict__ ei, int ne) {
    int e = blockIdx.x * blockDim.x + threadIdx.x;
    int is64 = (g_bad == 0);
    if (e < ne) {
        int d = getIdx(ei, ne + e, is64);
        atomicAdd(&g_deg[d], 1);
    }
}

#define SCB 256
__global__ void build_rows(int n) {
    __shared__ int sh[SCB];
    __shared__ int sbase;
    int t = threadIdx.x;
    int i = blockIdx.x * SCB + t;
    int d = (i < n) ? g_deg[i] : 0;
    sh[t] = d;
    __syncthreads();
    for (int off = 1; off < SCB; off <<= 1) {
        int v = (t >= off) ? sh[t - off] : 0;
        __syncthreads();
        sh[t] += v;
        __syncthreads();
    }
    if (t == SCB - 1) sbase = atomicAdd(&g_base, sh[SCB - 1]);
    __syncthreads();
    int excl = sh[t] - d;
    if (i < n) {
        g_rowstart[i] = sbase + excl;
        g_cursor[i] = sbase + excl;
    }
}

__global__ void csr_fill(const void* __restrict__ ei, int ne) {
    int e = blockIdx.x * blockDim.x + threadIdx.x;
    int is64 = (g_bad == 0);
    if (e < ne) {
        int s = getIdx(ei, e, is64);
        int d = getIdx(ei, ne + e, is64);
        int p = atomicAdd(&g_cursor[d], 1);
        g_csr[p] = s;
    }
}

// ---------------- operand prep (weights + x convert, one launch) -----------
__global__ void prep_all(const float* __restrict__ W1n,
                         const float* __restrict__ W1s,
                         const float* __restrict__ W2n,
                         const float* __restrict__ W2s,
                         const float* __restrict__ x, int K1, int nx4) {
    const int t1 = 512 * K1;
    const int tw = t1 + 512 * HID;
    const int total = tw + nx4;
    int stride = gridDim.x * blockDim.x;
    for (int idx = blockIdx.x * blockDim.x + threadIdx.x; idx < total;
         idx += stride) {
        if (idx < tw) {
            float v;
            __half* dh;
            int o;
            if (idx < t1) {
                int nrow = idx / K1, k = idx % K1;
                v = (nrow < 256) ? W1n[(size_t)k * 256 + nrow]
                                 : W1s[(size_t)k * 256 + (nrow - 256)];
                dh = g_WT1h; o = idx;
            } else {
                int j = idx - t1;
                int nrow = j / HID, k = j % HID;
                v = (nrow < 256) ? W2n[(size_t)k * 256 + nrow]
                                 : W2s[(size_t)k * 256 + (nrow - 256)];
                dh = g_WT2h; o = j;
            }
            dh[o] = __float2half(v);
        } else {
            int i = idx - tw;
            float4 v = ((const float4*)x)[i];
            __half h0 = __float2half(v.x);
            __half h1 = __float2half(v.y);
            __half h2 = __float2half(v.z);
            __half h3 = __float2half(v.w);
            uint32_t uh0 = (uint32_t)__half_as_ushort(h0) |
                           ((uint32_t)__half_as_ushort(h1) << 16);
            uint32_t uh1 = (uint32_t)__half_as_ushort(h2) |
                           ((uint32_t)__half_as_ushort(h3) << 16);
            ((uint2*)g_Ah)[i] = make_uint2(uh0, uh1);
        }
    }
}

// ---------------- HMMA dual GEMM, 128x256 tile, 3-stage cp.async -----------
__device__ __forceinline__ void mma16816(float* c, const uint32_t* a,
                                         const uint32_t* b) {
    asm volatile(
        "mma.sync.aligned.m16n8k16.row.col.f32.f16.f16.f32 "
        "{%0,%1,%2,%3}, {%4,%5,%6,%7}, {%8,%9}, {%0,%1,%2,%3};"
        : "+f"(c[0]), "+f"(c[1]), "+f"(c[2]), "+f"(c[3])
        : "r"(a[0]), "r"(a[1]), "r"(a[2]), "r"(a[3]), "r"(b[0]), "r"(b[1]));
}

#define SROW 20                       // u32 per row (80 B)
#define SROWB 80
#define TILE_A_U32 (128 * SROW)       // 2560
#define TILE_B_U32 (256 * SROW)       // 5120
#define STAGE_U32 (TILE_A_U32 + TILE_B_U32)  // 7680
#define NSTAGE 3
#define GEMM_SMEM (NSTAGE * STAGE_U32 * 4)   // 92160 B

__global__ __launch_bounds__(256, 1) void gemm_mma(
    int M, int K, int layer, const float* __restrict__ bias) {
    extern __shared__ uint32_t smem[];
    const uint32_t sb = smem_u32(smem);

    const __half* Ah = g_Ah;
    const __half* WTh = layer ? g_WT2h : g_WT1h;

    const int tid = threadIdx.x;
    const int wid = tid >> 5;
    const int lane = tid & 31;
    const int g = lane >> 2;
    const int tg = lane & 3;
    const int wm = wid >> 2;          // 0..1 (64 m each)
    const int wn = wid & 3;           // 0..3 (64 n each)
    const int bm = blockIdx.x * 128;
    const int bn = blockIdx.y * 256;  // 0 or 256 (buf select)

    const int sub = lane >> 3;
    const int rin = lane & 7;
    const uint32_t a_row_off = (uint32_t)(rin + (sub & 1) * 8) * SROWB +
                               (uint32_t)(sub >> 1) * 16;
    const uint32_t b_row_off = (uint32_t)(rin + (sub >> 1) * 8) * SROWB +
                               (uint32_t)(sub & 1) * 16;

    float acc[4][8][4];
#pragma unroll
    for (int i = 0; i < 4; i++)
#pragma unroll
        for (int j = 0; j < 8; j++)
#pragma unroll
            for (int q = 0; q < 4; q++) acc[i][j][q] = 0.f;

    const int nch = K >> 5;

    auto load_chunk = [&](int ch, int stg) {
        const int k0 = ch << 5;
        const uint32_t sbase = sb + stg * (STAGE_U32 * 4);
        // A tile: 128 rows x 32 halfs -> 512 16B slots
#pragma unroll
        for (int r = 0; r < 2; r++) {
            int lin = tid + r * 256;
            int row = lin >> 2;
            int q = lin & 3;
            uint32_t o = (row * SROW + q * 4) * 4;
            int gr = bm + row;   // always valid: g_Ah padded
            const __half* pa = Ah + (size_t)gr * K + k0 + q * 8;
            CP_ASYNC16(sbase + o, pa);
        }
        // B tile: 256 rows x 32 halfs -> 1024 16B slots
#pragma unroll
        for (int r = 0; r < 4; r++) {
            int lin = tid + r * 256;
            int row = lin >> 2;
            int q = lin & 3;
            uint32_t o = (row * SROW + q * 4) * 4;
            size_t gofs = (size_t)(bn + row) * K + k0 + q * 8;
            CP_ASYNC16(sbase + TILE_A_U32 * 4 + o, WTh + gofs);
        }
    };

    load_chunk(0, 0);
    CP_COMMIT();
    if (nch > 1) {
        load_chunk(1, 1);
        CP_COMMIT();
    }

    for (int ch = 0; ch < nch; ch++) {
        if (ch + 1 < nch) CP_WAIT(1); else CP_WAIT(0);
        __syncthreads();
        if (ch + 2 < nch) {
            load_chunk(ch + 2, (ch + 2) % NSTAGE);
            CP_COMMIT();
        }

        const uint32_t stg_b = sb + (ch % NSTAGE) * (STAGE_U32 * 4);
        const uint32_t aAh = stg_b;
        const uint32_t aBh = stg_b + TILE_A_U32 * 4;

#pragma unroll
        for (int ks = 0; ks < 2; ks++) {
            const uint32_t kofs = (uint32_t)ks * 32;
            uint32_t ah[4][4], bh[8][2];
#pragma unroll
            for (int mt = 0; mt < 4; mt++) {
                uint32_t rb = (uint32_t)(wm * 64 + mt * 16) * SROWB +
                              a_row_off + kofs;
                ldsm_x4(ah[mt], aAh + rb);
            }
#pragma unroll
            for (int p = 0; p < 4; p++) {
                uint32_t rb = (uint32_t)(wn * 64 + p * 16) * SROWB +
                              b_row_off + kofs;
                uint32_t t[4];
                ldsm_x4(t, aBh + rb);
                bh[2 * p][0] = t[0]; bh[2 * p][1] = t[1];
                bh[2 * p + 1][0] = t[2]; bh[2 * p + 1][1] = t[3];
            }
#pragma unroll
            for (int mt = 0; mt < 4; mt++)
#pragma unroll
                for (int nt = 0; nt < 8; nt++)
                    mma16816(acc[mt][nt], ah[mt], bh[nt]);
        }
    }

    // ---- epilogue: whole block writes one buffer ----
    __half* dst = (bn == 0) ? g_bufA : g_bufB;
    const bool addBias = (bn != 0);
#pragma unroll
    for (int mt = 0; mt < 4; mt++) {
        int r0 = bm + wm * 64 + mt * 16 + g;
#pragma unroll
        for (int nt = 0; nt < 8; nt++) {
            int cc = wn * 64 + nt * 8 + tg * 2;   // 0..255
            float b0 = 0.f, b1 = 0.f;
            if (addBias) { b0 = bias[cc]; b1 = bias[cc + 1]; }
            if (r0 < M) {
                __half2 v = __floats2half2_rn(acc[mt][nt][0] + b0,
                                              acc[mt][nt][1] + b1);
                *(__half2*)(dst + (size_t)r0 * HID + cc) = v;
            }
            if (r0 + 8 < M) {
                __half2 v = __floats2half2_rn(acc[mt][nt][2] + b0,
                                              acc[mt][nt][3] + b1);
                *(__half2*)(dst + (size_t)(r0 + 8) * HID + cc) = v;
            }
        }
    }
}

// ---- aggregation: 4 nodes/block x 64 threads; fp16 in/out, fp32 accum ----
// writes h (fp16) into g_Ah (row stride HID) — feeds next GEMM and pooling
__global__ void sage_aggregate(int n) {
    int node = blockIdx.x * 4 + (threadIdx.x >> 6);
    int c = (threadIdx.x & 63) * 4;
    if (node >= n) return;
    int s0 = g_rowstart[node];
    int d = g_deg[node];
    float4 acc = make_float4(0.f, 0.f, 0.f, 0.f);
#pragma unroll 4
    for (int j = 0; j < d; j++) {
        int s = g_csr[s0 + j];
        uint2 u = *(const uint2*)(g_bufA + (size_t)s * HID + c);
        float2 f0 = __half22float2(*(__half2*)&u.x);
        float2 f1 = __half22float2(*(__half2*)&u.y);
        acc.x += f0.x; acc.y += f0.y; acc.z += f1.x; acc.w += f1.y;
    }
    float inv = 1.0f / (float)(d > 0 ? d : 1);
    uint2 uw = *(const uint2*)(g_bufB + (size_t)node * HID + c);
    float2 w0 = __half22float2(*(__half2*)&uw.x);
    float2 w1 = __half22float2(*(__half2*)&uw.y);
    __half2 p0 = __floats2half2_rn(fmaxf(acc.x * inv + w0.x, 0.f),
                                   fmaxf(acc.y * inv + w0.y, 0.f));
    __half2 p1 = __floats2half2_rn(fmaxf(acc.z * inv + w1.x, 0.f),
                                   fmaxf(acc.w * inv + w1.y, 0.f));
    uint32_t u0 = *(uint32_t*)&p0;
    uint32_t u1 = *(uint32_t*)&p1;
    *(uint2*)(g_Ah + (size_t)node * HID + c) = make_uint2(u0, u1);
}

// ---------------- pooling / head ----------------
__device__ __forceinline__ int lower_bound_idx(const void* a, int n,
                                               int v, int is64) {
    int lo = 0, hi = n;
    while (lo < hi) {
        int mid = (lo + hi) >> 1;
        if (getIdx(a, mid, is64) < v) lo = mid + 1; else hi = mid;
    }
    return lo;
}

__global__ void pool_kernel(const void* __restrict__ batch, int n) {
    int g = blockIdx.x;
    int s = blockIdx.y;
    int S = gridDim.y;
    int is64 = (g_bad == 0);
    int lo = lower_bound_idx(batch, n, g, is64);
    int hi = lower_bound_idx(batch, n, g + 1, is64);
    int cnt = hi - lo;
    int chunk = (cnt + S - 1) / S;
    int a = lo + s * chunk;
    int b = a + chunk;
    if (b > hi) b = hi;
    int c = threadIdx.x;
    float acc = 0.f;
    for (int i = a; i < b; i++)
        acc += __half2float(g_Ah[(size_t)i * HID + c]);
    if (a < b) atomicAdd(&g_pool[g * HID + c], acc);
}

__global__ void head_kernel(const void* __restrict__ batch, int n,
                            const float* __restrict__ fc1w,
                            const float* __restrict__ fc1b,
                            const float* __restrict__ fc2w,
                            const float* __restrict__ fc2b,
                            float* __restrict__ out) {
    __shared__ float pooled[HID];
    __shared__ float t1[HID / 2];
    int t = threadIdx.x;  // 256
    int g = blockIdx.x;   // 16 blocks
    int is64 = (g_bad == 0);
    int lo = lower_bound_idx(batch, n, g, is64);
    int hi = lower_bound_idx(batch, n, g + 1, is64);
    float cnt = fmaxf((float)(hi - lo), 1.0f);
    pooled[t] = g_pool[g * HID + t] / cnt;
    __syncthreads();
    if (t < HID / 2) {
        float s = fc1b[t];
        for (int c = 0; c < HID; c++) s += pooled[c] * fc1w[c * (HID / 2) + t];
        t1[t] = fmaxf(s, 0.f);
    }
    __syncthreads();
    if (t < 2) {
        float s = fc2b[t];
        for (int j = 0; j < HID / 2; j++) s += t1[j] * fc2w[j * 2 + t];
        out[g * 2 + t] = s;
    }
}

// ---------------- launch ----------------
extern "C" void kernel_launch(void* const* d_in, const int* in_sizes, int n_in,
                              void* d_out, int out_size) {
    const float* x = (const float*)d_in[0];
    const void* ei = d_in[1];
    const void* batch = d_in[2];
    const float* W1n = (const float*)d_in[3];
    const float* W1s = (const float*)d_in[4];
    const float* b1 = (const float*)d_in[5];
    const float* W2n = (const float*)d_in[6];
    const float* W2s = (const float*)d_in[7];
    const float* b2 = (const float*)d_in[8];
    const float* fc1w = (const float*)d_in[9];
    const float* fc1b = (const float*)d_in[10];
    const float* fc2w = (const float*)d_in[11];
    const float* fc2b = (const float*)d_in[12];
    float* out = (float*)d_out;

    const int n = in_sizes[2];            // 20000 nodes
    const int in_dim = in_sizes[0] / n;   // 512
    const int ne = in_sizes[1] / 2;       // 160000 edges

    static cudaStream_t s2 = nullptr;
    static cudaEvent_t evF = nullptr, evJ = nullptr;
    static int attr_set = 0;
    if (!attr_set) {
        cudaFuncSetAttribute(gemm_mma,
                             cudaFuncAttributeMaxDynamicSharedMemorySize,
                             GEMM_SMEM);
        cudaStreamCreateWithFlags(&s2, cudaStreamNonBlocking);
        cudaEventCreateWithFlags(&evF, cudaEventDisableTiming);
        cudaEventCreateWithFlags(&evJ, cudaEventDisableTiming);
        attr_set = 1;
    }

    const int nb = (n + SCB - 1) / SCB;

    // main stream: init -> hist -> prep -> gemm1
    init_kernel<<<160, 256>>>(ei, ne, n);
    edge_hist<<<(ne + 255) / 256, 256>>>(ei, ne);

    // fork: CSR finishing (rows + fill) runs concurrently with prep+gemm1
    cudaEventRecord(evF, 0);
    cudaStreamWaitEvent(s2, evF, 0);
    build_rows<<<nb, SCB, 0, s2>>>(n);
    csr_fill<<<(ne + 255) / 256, 256, 0, s2>>>(ei, ne);
    cudaEventRecord(evJ, s2);

    prep_all<<<592, 256>>>(W1n, W1s, W2n, W2s, x, in_dim, n * in_dim / 4);

    dim3 g1((n + 127) / 128, 2);
    gemm_mma<<<g1, 256, GEMM_SMEM>>>(n, in_dim, 0, b1);

    // join: aggregation needs the CSR
    cudaStreamWaitEvent(0, evJ, 0);
    sage_aggregate<<<(n + 3) / 4, 256>>>(n);

    gemm_mma<<<g1, 256, GEMM_SMEM>>>(n, HID, 1, b2);
    sage_aggregate<<<(n + 3) / 4, 256>>>(n);

    dim3 gp(NUM_GRAPHS, 32);
    pool_kernel<<<gp, HID>>>(batch, n);
    head_kernel<<<NUM_GRAPHS, HID>>>(batch, n, fc1w, fc1b, fc2w, fc2b, out);
}

// round 17
// speedup vs baseline: 1.1368x; 1.1368x over previous
#include <cuda_runtime.h>
#include <cuda_fp16.h>
#include <cstdint>

#define MAX_NODES 20000
#define MAX_EDGES 160000
#define HID 256
#define NUM_GRAPHS 16

// ---------------- device scratch (static, no runtime alloc) ----------------
__device__ __half g_bufA[MAX_NODES * HID];  // y_nbr projections (fp16)
__device__ __half g_bufB[MAX_NODES * HID];  // y_self projections +bias (fp16)
__device__ int    g_deg[MAX_NODES];
__device__ int    g_rowstart[MAX_NODES];
__device__ int    g_cursor[MAX_NODES];
__device__ int    g_csr[MAX_EDGES];
__device__ float  g_pool[NUM_GRAPHS * HID];
__device__ int    g_bad;                    // !=0 -> index inputs are int32
__device__ int    g_base;                   // CSR allocation ticket

// A operand fp16 (padded); also holds h1/h2 between layers
#define PAD_ROWS (MAX_NODES + 128)
__device__ __half g_Ah[PAD_ROWS * 512];

// transposed fp16 weights: WT[n][k], n in [0,512)
__device__ __half g_WT1h[512 * 512];
__device__ __half g_WT2h[512 * 256];

// ---------------- helpers ----------------
__device__ __forceinline__ uint32_t smem_u32(const void* p) {
    uint32_t a;
    asm("{ .reg .u64 t; cvta.to.shared.u64 t, %1; cvt.u32.u64 %0, t; }"
        : "=r"(a) : "l"(p));
    return a;
}
#define CP_ASYNC16(dst_u32, src_ptr) \
    asm volatile("cp.async.cg.shared.global [%0], [%1], 16;" \
                 :: "r"(dst_u32), "l"(src_ptr))
#define CP_COMMIT() asm volatile("cp.async.commit_group;" ::: "memory")
#define CP_WAIT(N) asm volatile("cp.async.wait_group %0;" :: "n"(N) : "memory")

__device__ __forceinline__ void ldsm_x4(uint32_t* r, uint32_t addr) {
    asm volatile(
        "ldmatrix.sync.aligned.m8n8.x4.shared.b16 {%0,%1,%2,%3}, [%4];"
        : "=r"(r[0]), "=r"(r[1]), "=r"(r[2]), "=r"(r[3]) : "r"(addr));
}

__device__ __forceinline__ int getIdx(const void* p, int i, int is64) {
    if (is64) return (int)((const long long*)p)[i];
    return ((const int*)p)[i];
}

// ---------------- init: zero + dtype probe (one launch) ----------------
__global__ void init_kernel(const void* ei, int ne, int n) {
    int i = blockIdx.x * blockDim.x + threadIdx.x;
    int stride = gridDim.x * blockDim.x;
    if (i == 0) { g_base = 0; }
    for (int j = i; j < n; j += stride) g_deg[j] = 0;
    for (int j = i; j < NUM_GRAPHS * HID; j += stride) g_pool[j] = 0.0f;
    int local = 0;
    for (int e = i; e < ne; e += stride) {
        long long v = ((const long long*)ei)[e];
        if (v < 0 || v >= (long long)n) local = 1;
    }
    if (i == 0) g_bad = 0;
    __threadfence();
    if (__syncthreads_or(local)) {
        if (threadIdx.x == 0) atomicOr(&g_bad, 1);
    }
}

// ---------------- CSR build ----------------
__global__ void edge_hist(const void* __restrict__ ei, int ne) {
    int e = blockIdx.x * blockDim.x + threadIdx.x;
    int is64 = (g_bad == 0);
    if (e < ne) {
        int d = getIdx(ei, ne + e, is64);
        atomicAdd(&g_deg[d], 1);
    }
}

#define SCB 256
__global__ void build_rows(int n) {
    __shared__ int sh[SCB];
    __shared__ int sbase;
    int t = threadIdx.x;
    int i = blockIdx.x * SCB + t;
    int d = (i < n) ? g_deg[i] : 0;
    sh[t] = d;
    __syncthreads();
    for (int off = 1; off < SCB; off <<= 1) {
        int v = (t >= off) ? sh[t - off] : 0;
        __syncthreads();
        sh[t] += v;
        __syncthreads();
    }
    if (t == SCB - 1) sbase = atomicAdd(&g_base, sh[SCB - 1]);
    __syncthreads();
    int excl = sh[t] - d;
    if (i < n) {
        g_rowstart[i] = sbase + excl;
        g_cursor[i] = sbase + excl;
    }
}

__global__ void csr_fill(const void* __restrict__ ei, int ne) {
    int e = blockIdx.x * blockDim.x + threadIdx.x;
    int is64 = (g_bad == 0);
    if (e < ne) {
        int s = getIdx(ei, e, is64);
        int d = getIdx(ei, ne + e, is64);
        int p = atomicAdd(&g_cursor[d], 1);
        g_csr[p] = s;
    }
}

// ---------------- operand prep (weights + x convert, one launch) -----------
__global__ void prep_all(const float* __restrict__ W1n,
                         const float* __restrict__ W1s,
                         const float* __restrict__ W2n,
                         const float* __restrict__ W2s,
                         const float* __restrict__ x, int K1, int nx4) {
    const int t1 = 512 * K1;
    const int tw = t1 + 512 * HID;
    const int total = tw + nx4;
    int stride = gridDim.x * blockDim.x;
    for (int idx = blockIdx.x * blockDim.x + threadIdx.x; idx < total;
         idx += stride) {
        if (idx < tw) {
            float v;
            __half* dh;
            int o;
            if (idx < t1) {
                int nrow = idx / K1, k = idx % K1;
                v = (nrow < 256) ? W1n[(size_t)k * 256 + nrow]
                                 : W1s[(size_t)k * 256 + (nrow - 256)];
                dh = g_WT1h; o = idx;
            } else {
                int j = idx - t1;
                int nrow = j / HID, k = j % HID;
                v = (nrow < 256) ? W2n[(size_t)k * 256 + nrow]
                                 : W2s[(size_t)k * 256 + (nrow - 256)];
                dh = g_WT2h; o = j;
            }
            dh[o] = __float2half(v);
        } else {
            int i = idx - tw;
            float4 v = ((const float4*)x)[i];
            __half h0 = __float2half(v.x);
            __half h1 = __float2half(v.y);
            __half h2 = __float2half(v.z);
            __half h3 = __float2half(v.w);
            uint32_t uh0 = (uint32_t)__half_as_ushort(h0) |
                           ((uint32_t)__half_as_ushort(h1) << 16);
            uint32_t uh1 = (uint32_t)__half_as_ushort(h2) |
                           ((uint32_t)__half_as_ushort(h3) << 16);
            ((uint2*)g_Ah)[i] = make_uint2(uh0, uh1);
        }
    }
}

// ---------------- HMMA dual GEMM, 128x128 tile, 4-stage cp.async -----------
__device__ __forceinline__ void mma16816(float* c, const uint32_t* a,
                                         const uint32_t* b) {
    asm volatile(
        "mma.sync.aligned.m16n8k16.row.col.f32.f16.f16.f32 "
        "{%0,%1,%2,%3}, {%4,%5,%6,%7}, {%8,%9}, {%0,%1,%2,%3};"
        : "+f"(c[0]), "+f"(c[1]), "+f"(c[2]), "+f"(c[3])
        : "r"(a[0]), "r"(a[1]), "r"(a[2]), "r"(a[3]), "r"(b[0]), "r"(b[1]));
}

#define SROW 20                       // u32 per row (80 B)
#define SROWB 80
#define TILE_U32 (128 * SROW)
#define STAGE_U32 (2 * TILE_U32)      // A, B
#define NSTAGE 4
#define GEMM_SMEM (NSTAGE * STAGE_U32 * 4) // 81920 B

__global__ __launch_bounds__(256, 2) void gemm_mma(
    int M, int K, int layer, const float* __restrict__ bias) {
    extern __shared__ uint32_t smem[];
    const uint32_t sb = smem_u32(smem);

    const __half* Ah = g_Ah;
    const __half* WTh = layer ? g_WT2h : g_WT1h;

    const int tid = threadIdx.x;
    const int wid = tid >> 5;
    const int lane = tid & 31;
    const int g = lane >> 2;
    const int tg = lane & 3;
    const int wm = wid >> 2;
    const int wn = wid & 3;
    const int bm = blockIdx.x * 128;
    const int bn = blockIdx.y * 128;

    const int sub = lane >> 3;
    const int rin = lane & 7;
    const uint32_t a_row_off = (uint32_t)(rin + (sub & 1) * 8) * SROWB +
                               (uint32_t)(sub >> 1) * 16;
    const uint32_t b_row_off = (uint32_t)(rin + (sub >> 1) * 8) * SROWB +
                               (uint32_t)(sub & 1) * 16;

    float acc[4][4][4];
#pragma unroll
    for (int i = 0; i < 4; i++)
#pragma unroll
        for (int j = 0; j < 4; j++)
#pragma unroll
            for (int q = 0; q < 4; q++) acc[i][j][q] = 0.f;

    const int nch = K >> 5;

    auto load_chunk = [&](int ch, int stg) {
        const int k0 = ch << 5;
        const uint32_t sbase = sb + stg * (STAGE_U32 * 4);
#pragma unroll
        for (int r = 0; r < 2; r++) {
            int lin = tid + r * 256;
            int row = lin >> 2;
            int q = lin & 3;
            uint32_t o = (row * SROW + q * 4) * 4;
            int gr = bm + row;   // always valid: g_Ah padded
            const __half* pa = Ah + (size_t)gr * K + k0 + q * 8;
            CP_ASYNC16(sbase + o, pa);
            size_t gofs = (size_t)(bn + row) * K + k0 + q * 8;
            CP_ASYNC16(sbase + TILE_U32 * 4 + o, WTh + gofs);
        }
    };

    // prologue: prefetch up to 3 chunks
    {
        int npre = (nch < NSTAGE - 1) ? nch : (NSTAGE - 1);
        for (int p = 0; p < npre; p++) {
            load_chunk(p, p);
            CP_COMMIT();
        }
    }

    for (int ch = 0; ch < nch; ch++) {
        // groups pending beyond chunk ch
        int pend = ((nch < ch + NSTAGE - 1) ? nch : (ch + NSTAGE - 1)) - ch - 1;
        if (pend >= 2) CP_WAIT(2);
        else if (pend == 1) CP_WAIT(1);
        else CP_WAIT(0);
        __syncthreads();
        if (ch + NSTAGE - 1 < nch) {
            load_chunk(ch + NSTAGE - 1, (ch + NSTAGE - 1) % NSTAGE);
            CP_COMMIT();
        }

        const uint32_t stg_b = sb + (ch % NSTAGE) * (STAGE_U32 * 4);
        const uint32_t aAh = stg_b;
        const uint32_t aBh = stg_b + TILE_U32 * 4;

#pragma unroll
        for (int ks = 0; ks < 2; ks++) {
            const uint32_t kofs = (uint32_t)ks * 32;
            uint32_t ah[4][4], bh[4][2];
#pragma unroll
            for (int mt = 0; mt < 4; mt++) {
                uint32_t rb = (uint32_t)(wm * 64 + mt * 16) * SROWB +
                              a_row_off + kofs;
                ldsm_x4(ah[mt], aAh + rb);
            }
#pragma unroll
            for (int p = 0; p < 2; p++) {
                uint32_t rb = (uint32_t)(wn * 32 + p * 16) * SROWB +
                              b_row_off + kofs;
                uint32_t t[4];
                ldsm_x4(t, aBh + rb);
                bh[2 * p][0] = t[0]; bh[2 * p][1] = t[1];
                bh[2 * p + 1][0] = t[2]; bh[2 * p + 1][1] = t[3];
            }
#pragma unroll
            for (int mt = 0; mt < 4; mt++)
#pragma unroll
                for (int nt = 0; nt < 4; nt++)
                    mma16816(acc[mt][nt], ah[mt], bh[nt]);
        }
    }

    // ---- epilogue: packed half2 stores ----
#pragma unroll
    for (int mt = 0; mt < 4; mt++) {
        int r0 = bm + wm * 64 + mt * 16 + g;
#pragma unroll
        for (int nt = 0; nt < 4; nt++) {
            int c = bn + wn * 32 + nt * 8 + tg * 2;
            float b0 = 0.f, b1 = 0.f;
            __half* dst;
            int cc = c;
            if (c >= 256) {
                cc = c - 256;
                b0 = bias[cc];
                b1 = bias[cc + 1];
                dst = g_bufB;
            } else {
                dst = g_bufA;
            }
            if (r0 < M) {
                __half2 v = __floats2half2_rn(acc[mt][nt][0] + b0,
                                              acc[mt][nt][1] + b1);
                *(__half2*)(dst + (size_t)r0 * HID + cc) = v;
            }
            if (r0 + 8 < M) {
                __half2 v = __floats2half2_rn(acc[mt][nt][2] + b0,
                                              acc[mt][nt][3] + b1);
                *(__half2*)(dst + (size_t)(r0 + 8) * HID + cc) = v;
            }
        }
    }
}

// ---- aggregation: 4 nodes/block x 64 threads; fp16 in/out, fp32 accum ----
// writes h (fp16) into g_Ah — feeds next GEMM and pooling
__global__ void sage_aggregate(int n) {
    int node = blockIdx.x * 4 + (threadIdx.x >> 6);
    int c = (threadIdx.x & 63) * 4;
    if (node >= n) return;
    int s0 = g_rowstart[node];
    int d = g_deg[node];
    float4 acc = make_float4(0.f, 0.f, 0.f, 0.f);
#pragma unroll 4
    for (int j = 0; j < d; j++) {
        int s = g_csr[s0 + j];
        uint2 u = *(const uint2*)(g_bufA + (size_t)s * HID + c);
        float2 f0 = __half22float2(*(__half2*)&u.x);
        float2 f1 = __half22float2(*(__half2*)&u.y);
        acc.x += f0.x; acc.y += f0.y; acc.z += f1.x; acc.w += f1.y;
    }
    float inv = 1.0f / (float)(d > 0 ? d : 1);
    uint2 uw = *(const uint2*)(g_bufB + (size_t)node * HID + c);
    float2 w0 = __half22float2(*(__half2*)&uw.x);
    float2 w1 = __half22float2(*(__half2*)&uw.y);
    __half2 p0 = __floats2half2_rn(fmaxf(acc.x * inv + w0.x, 0.f),
                                   fmaxf(acc.y * inv + w0.y, 0.f));
    __half2 p1 = __floats2half2_rn(fmaxf(acc.z * inv + w1.x, 0.f),
                                   fmaxf(acc.w * inv + w1.y, 0.f));
    uint32_t u0 = *(uint32_t*)&p0;
    uint32_t u1 = *(uint32_t*)&p1;
    *(uint2*)(g_Ah + (size_t)node * HID + c) = make_uint2(u0, u1);
}

// ---------------- pooling / head ----------------
__device__ __forceinline__ int lower_bound_idx(const void* a, int n,
                                               int v, int is64) {
    int lo = 0, hi = n;
    while (lo < hi) {
        int mid = (lo + hi) >> 1;
        if (getIdx(a, mid, is64) < v) lo = mid + 1; else hi = mid;
    }
    return lo;
}

__global__ void pool_kernel(const void* __restrict__ batch, int n) {
    int g = blockIdx.x;
    int s = blockIdx.y;
    int S = gridDim.y;
    int is64 = (g_bad == 0);
    int lo = lower_bound_idx(batch, n, g, is64);
    int hi = lower_bound_idx(batch, n, g + 1, is64);
    int cnt = hi - lo;
    int chunk = (cnt + S - 1) / S;
    int a = lo + s * chunk;
    int b = a + chunk;
    if (b > hi) b = hi;
    int c = threadIdx.x;
    float acc = 0.f;
    for (int i = a; i < b; i++)
        acc += __half2float(g_Ah[(size_t)i * HID + c]);
    if (a < b) atomicAdd(&g_pool[g * HID + c], acc);
}

__global__ void head_kernel(const void* __restrict__ batch, int n,
                            const float* __restrict__ fc1w,
                            const float* __restrict__ fc1b,
                            const float* __restrict__ fc2w,
                            const float* __restrict__ fc2b,
                            float* __restrict__ out) {
    __shared__ float pooled[HID];
    __shared__ float t1[HID / 2];
    int t = threadIdx.x;  // 256
    int g = blockIdx.x;   // 16 blocks
    int is64 = (g_bad == 0);
    int lo = lower_bound_idx(batch, n, g, is64);
    int hi = lower_bound_idx(batch, n, g + 1, is64);
    float cnt = fmaxf((float)(hi - lo), 1.0f);
    pooled[t] = g_pool[g * HID + t] / cnt;
    __syncthreads();
    if (t < HID / 2) {
        float s = fc1b[t];
        for (int c = 0; c < HID; c++) s += pooled[c] * fc1w[c * (HID / 2) + t];
        t1[t] = fmaxf(s, 0.f);
    }
    __syncthreads();
    if (t < 2) {
        float s = fc2b[t];
        for (int j = 0; j < HID / 2; j++) s += t1[j] * fc2w[j * 2 + t];
        out[g * 2 + t] = s;
    }
}

// ---------------- launch ----------------
extern "C" void kernel_launch(void* const* d_in, const int* in_sizes, int n_in,
                              void* d_out, int out_size) {
    const float* x = (const float*)d_in[0];
    const void* ei = d_in[1];
    const void* batch = d_in[2];
    const float* W1n = (const float*)d_in[3];
    const float* W1s = (const float*)d_in[4];
    const float* b1 = (const float*)d_in[5];
    const float* W2n = (const float*)d_in[6];
    const float* W2s = (const float*)d_in[7];
    const float* b2 = (const float*)d_in[8];
    const float* fc1w = (const float*)d_in[9];
    const float* fc1b = (const float*)d_in[10];
    const float* fc2w = (const float*)d_in[11];
    const float* fc2b = (const float*)d_in[12];
    float* out = (float*)d_out;

    const int n = in_sizes[2];            // 20000 nodes
    const int in_dim = in_sizes[0] / n;   // 512
    const int ne = in_sizes[1] / 2;       // 160000 edges

    static cudaStream_t s2 = nullptr;
    static cudaEvent_t evF = nullptr, evJ = nullptr;
    static int attr_set = 0;
    if (!attr_set) {
        cudaFuncSetAttribute(gemm_mma,
                             cudaFuncAttributeMaxDynamicSharedMemorySize,
                             GEMM_SMEM);
        cudaStreamCreateWithFlags(&s2, cudaStreamNonBlocking);
        cudaEventCreateWithFlags(&evF, cudaEventDisableTiming);
        cudaEventCreateWithFlags(&evJ, cudaEventDisableTiming);
        attr_set = 1;
    }

    const int nb = (n + SCB - 1) / SCB;

    // main stream: init -> hist -> prep -> gemm1
    init_kernel<<<160, 256>>>(ei, ne, n);
    edge_hist<<<(ne + 255) / 256, 256>>>(ei, ne);

    // fork: CSR finishing (rows + fill) runs concurrently with prep+gemm1
    cudaEventRecord(evF, 0);
    cudaStreamWaitEvent(s2, evF, 0);
    build_rows<<<nb, SCB, 0, s2>>>(n);
    csr_fill<<<(ne + 255) / 256, 256, 0, s2>>>(ei, ne);
    cudaEventRecord(evJ, s2);

    prep_all<<<592, 256>>>(W1n, W1s, W2n, W2s, x, in_dim, n * in_dim / 4);

    dim3 g1((n + 127) / 128, 4);
    gemm_mma<<<g1, 256, GEMM_SMEM>>>(n, in_dim, 0, b1);

    // join: aggregation needs the CSR
    cudaStreamWaitEvent(0, evJ, 0);
    sage_aggregate<<<(n + 3) / 4, 256>>>(n);

    gemm_mma<<<g1, 256, GEMM_SMEM>>>(n, HID, 1, b2);
    sage_aggregate<<<(n + 3) / 4, 256>>>(n);

    dim3 gp(NUM_GRAPHS, 32);
    pool_kernel<<<gp, HID>>>(batch, n);
    head_kernel<<<NUM_GRAPHS, HID>>>(batch, n, fc1w, fc1b, fc2w, fc2b, out);
}